// round 1
// baseline (speedup 1.0000x reference)
#include <cuda_runtime.h>

#define FULLMASK 0xffffffffu

constexpr int Bsz  = 4096;
constexpr int Ln   = 50;
constexpr int Dm   = 64;
constexpr int ROWS = Bsz * Ln;   // 204800

// ---------------- scratch (static device allocations are allowed) ----------
__device__ float g_fjt[ROWS * Dm];     // [B*L, 64]
__device__ float g_scores[ROWS];       // [B*L]

// ---------------- helpers --------------------------------------------------
__device__ __forceinline__ float wredmax(float v) {
#pragma unroll
    for (int o = 16; o; o >>= 1) v = fmaxf(v, __shfl_xor_sync(FULLMASK, v, o));
    return v;
}
__device__ __forceinline__ float wredsum(float v) {
#pragma unroll
    for (int o = 16; o; o >>= 1) v += __shfl_xor_sync(FULLMASK, v, o);
    return v;
}
__device__ __forceinline__ void cpf(float* dst, const float* __restrict__ src, int n) {
    for (int i = threadIdx.x; i < n; i += blockDim.x) dst[i] = src[i];
}

// 4-row register-blocked MLP layer: xb holds 4 rows of 128 floats (stride 128).
// Input vector length K in xb[r*128 + 0..K). Output (64 wide) written back to
// xb[r*128 + 0..63]. Lane j produces cols j and j+32.
template <int K, bool RELU>
__device__ __forceinline__ void mlp4(const float* __restrict__ W,
                                     const float* __restrict__ bias,
                                     float* __restrict__ xb, int j) {
    float a00 = 0.f, a01 = 0.f, a10 = 0.f, a11 = 0.f;
    float a20 = 0.f, a21 = 0.f, a30 = 0.f, a31 = 0.f;
#pragma unroll 8
    for (int k = 0; k < K; k++) {
        float w0 = W[k * Dm + j];
        float w1 = W[k * Dm + j + 32];
        float x0 = xb[k];
        float x1 = xb[128 + k];
        float x2 = xb[256 + k];
        float x3 = xb[384 + k];
        a00 = fmaf(x0, w0, a00); a01 = fmaf(x0, w1, a01);
        a10 = fmaf(x1, w0, a10); a11 = fmaf(x1, w1, a11);
        a20 = fmaf(x2, w0, a20); a21 = fmaf(x2, w1, a21);
        a30 = fmaf(x3, w0, a30); a31 = fmaf(x3, w1, a31);
    }
    float b0 = bias[j], b1 = bias[j + 32];
    a00 += b0; a01 += b1; a10 += b0; a11 += b1;
    a20 += b0; a21 += b1; a30 += b0; a31 += b1;
    if (RELU) {
        a00 = fmaxf(a00, 0.f); a01 = fmaxf(a01, 0.f);
        a10 = fmaxf(a10, 0.f); a11 = fmaxf(a11, 0.f);
        a20 = fmaxf(a20, 0.f); a21 = fmaxf(a21, 0.f);
        a30 = fmaxf(a30, 0.f); a31 = fmaxf(a31, 0.f);
    }
    __syncwarp();
    xb[j]        = a00; xb[j + 32]        = a01;
    xb[128 + j]  = a10; xb[128 + j + 32]  = a11;
    xb[256 + j]  = a20; xb[256 + j + 32]  = a21;
    xb[384 + j]  = a30; xb[384 + j + 32]  = a31;
    __syncwarp();
}

// Single-row MLP layer (for K2). Input xb[0..K), output returned in o0/o1.
template <int K, bool RELU>
__device__ __forceinline__ void mlp1(const float* __restrict__ W,
                                     const float* __restrict__ bias,
                                     const float* __restrict__ xb, int lane,
                                     float& o0, float& o1) {
    float c0 = 0.f, c1 = 0.f;
#pragma unroll 8
    for (int k = 0; k < K; k++) {
        float x = xb[k];
        c0 = fmaf(x, W[k * Dm + lane], c0);
        c1 = fmaf(x, W[k * Dm + lane + 32], c1);
    }
    c0 += bias[lane]; c1 += bias[lane + 32];
    if (RELU) { c0 = fmaxf(c0, 0.f); c1 = fmaxf(c1, 0.f); }
    o0 = c0; o1 = c1;
}

// ---------------- K1: per-row fusion MLP + attention scores ----------------
// smem layout (floats)
constexpr int OFF_GV1  = 0;            // 8192
constexpr int OFF_GV2  = 8192;         // 4096
constexpr int OFF_GV3  = 12288;        // 4096
constexpr int OFF_AT1  = 16384;        // 8192
constexpr int OFF_AT2  = 24576;        // 4096
constexpr int OFF_AT3  = 28672;        // 64
constexpr int OFF_BGV1 = 28736;
constexpr int OFF_BGV2 = 28800;
constexpr int OFF_BGV3 = 28864;
constexpr int OFF_BAT1 = 28928;
constexpr int OFF_BAT2 = 28992;
constexpr int OFF_BAT3 = 29056;        // 1
constexpr int OFF_XB1  = 29088;        // 16 warps * 512 floats
constexpr int SMEM1_FLOATS = OFF_XB1 + 16 * 512;   // 37280 floats = 149120 B

__global__ __launch_bounds__(512, 1)
void k_rows(const int* __restrict__ nodes_v, const int* __restrict__ neigh_u,
            const int* __restrict__ neigh_r,
            const float* __restrict__ embed_u, const float* __restrict__ embed_i,
            const float* __restrict__ embed_r,
            const float* __restrict__ gw1, const float* __restrict__ gb1,
            const float* __restrict__ gw2, const float* __restrict__ gb2,
            const float* __restrict__ gw3, const float* __restrict__ gb3,
            const float* __restrict__ aw1, const float* __restrict__ ab1,
            const float* __restrict__ aw2, const float* __restrict__ ab2,
            const float* __restrict__ aw3, const float* __restrict__ ab3) {
    extern __shared__ float sm[];
    cpf(sm + OFF_GV1, gw1, 8192);
    cpf(sm + OFF_GV2, gw2, 4096);
    cpf(sm + OFF_GV3, gw3, 4096);
    cpf(sm + OFF_AT1, aw1, 8192);
    cpf(sm + OFF_AT2, aw2, 4096);
    cpf(sm + OFF_AT3, aw3, 64);
    cpf(sm + OFF_BGV1, gb1, 64);
    cpf(sm + OFF_BGV2, gb2, 64);
    cpf(sm + OFF_BGV3, gb3, 64);
    cpf(sm + OFF_BAT1, ab1, 64);
    cpf(sm + OFF_BAT2, ab2, 64);
    if (threadIdx.x == 0) sm[OFF_BAT3] = ab3[0];
    __syncthreads();

    const int wid  = threadIdx.x >> 5;
    const int lane = threadIdx.x & 31;
    float* xb = sm + OFF_XB1 + wid * 512;   // 4 rows x 128

    const int NTILES = ROWS / 64;   // 3200, ROWS % 64 == 0
    for (int tile = blockIdx.x; tile < NTILES; tile += gridDim.x) {
        const int row0 = tile * 64 + wid * 4;
        int ivr[4];
        // gather x = [pt | er] for 4 rows
#pragma unroll
        for (int r = 0; r < 4; r++) {
            int row = row0 + r;
            int b   = row / Ln;
            int u   = neigh_u[row];
            int rr  = neigh_r[row];
            ivr[r]  = nodes_v[b];
            float2 pu = ((const float2*)embed_u)[u  * 32 + lane];
            float2 pe = ((const float2*)embed_r)[rr * 32 + lane];
            ((float2*)(xb + r * 128))[lane]      = pu;
            ((float2*)(xb + r * 128 + 64))[lane] = pe;
        }
        __syncwarp();

        mlp4<128, true >(sm + OFF_GV1, sm + OFF_BGV1, xb, lane);
        mlp4<64,  true >(sm + OFF_GV2, sm + OFF_BGV2, xb, lane);
        mlp4<64,  false>(sm + OFF_GV3, sm + OFF_BGV3, xb, lane);

        // write fjt to global; place qj into the upper half of each row buffer
#pragma unroll
        for (int r = 0; r < 4; r++) {
            int row = row0 + r;
            float f0 = xb[r * 128 + lane];
            float f1 = xb[r * 128 + lane + 32];
            g_fjt[row * Dm + lane]      = f0;
            g_fjt[row * Dm + lane + 32] = f1;
            float2 q = ((const float2*)embed_i)[ivr[r] * 32 + lane];
            ((float2*)(xb + r * 128 + 64))[lane] = q;
        }
        __syncwarp();

        mlp4<128, true>(sm + OFF_AT1, sm + OFF_BAT1, xb, lane);
        mlp4<64,  true>(sm + OFF_AT2, sm + OFF_BAT2, xb, lane);

        const float w30 = sm[OFF_AT3 + lane];
        const float w31 = sm[OFF_AT3 + lane + 32];
        const float b3  = sm[OFF_BAT3];
#pragma unroll
        for (int r = 0; r < 4; r++) {
            float s = xb[r * 128 + lane] * w30 + xb[r * 128 + lane + 32] * w31;
            s = wredsum(s);
            if (lane == 0) g_scores[row0 + r] = s + b3;
        }
        __syncwarp();
    }
}

// ---------------- K2: softmax + aggregation + combine MLP ------------------
constexpr int OFF_W1  = 0;         // 8192
constexpr int OFF_W2  = 8192;      // 4096
constexpr int OFF_B1  = 12288;     // 64
constexpr int OFF_B2  = 12352;     // 64
constexpr int OFF_XB2 = 12416;     // 8 warps * 128
constexpr int OFF_MU  = 12416 + 8 * 128;   // 8 warps * 64
constexpr int SMEM2_FLOATS = OFF_MU + 8 * 64;  // 13952 floats = 55808 B

__global__ __launch_bounds__(256, 1)
void k_agg(const int* __restrict__ nodes_v, const float* __restrict__ embed_i,
           const float* __restrict__ w1, const float* __restrict__ b1,
           const float* __restrict__ w2, const float* __restrict__ b2,
           float* __restrict__ out) {
    extern __shared__ float sm[];
    cpf(sm + OFF_W1, w1, 8192);
    cpf(sm + OFF_W2, w2, 4096);
    cpf(sm + OFF_B1, b1, 64);
    cpf(sm + OFF_B2, b2, 64);
    __syncthreads();

    const int wid  = threadIdx.x >> 5;
    const int lane = threadIdx.x & 31;
    const int nw   = blockDim.x >> 5;
    float* xb = sm + OFF_XB2 + wid * 128;
    float* mu = sm + OFF_MU  + wid * 64;

    for (int b = blockIdx.x * nw + wid; b < Bsz; b += gridDim.x * nw) {
        // softmax over L=50 scores
        const float* sc = g_scores + b * Ln;
        float s0 = (lane < Ln)        ? sc[lane]      : -1e30f;
        float s1 = ((lane + 32) < Ln) ? sc[lane + 32] : -1e30f;
        float m  = wredmax(fmaxf(s0, s1));
        float e0 = (lane < Ln)        ? expf(s0 - m) : 0.f;
        float e1 = ((lane + 32) < Ln) ? expf(s1 - m) : 0.f;
        float inv = 1.f / wredsum(e0 + e1);
        mu[lane]      = e0 * inv;
        mu[lane + 32] = e1 * inv;
        __syncwarp();

        // zj = sum_l mu[l] * fjt[b,l,:]
        float a0 = 0.f, a1 = 0.f;
        const float* fj = g_fjt + (long)b * Ln * Dm;
#pragma unroll 2
        for (int l = 0; l < Ln; l++) {
            float mm = mu[l];
            a0 = fmaf(mm, fj[l * Dm + lane], a0);
            a1 = fmaf(mm, fj[l * Dm + lane + 32], a1);
        }
        xb[lane]      = a0;
        xb[lane + 32] = a1;
        int iv = nodes_v[b];
        ((float2*)(xb + 64))[lane] = ((const float2*)embed_i)[iv * 32 + lane];
        __syncwarp();

        float z0, z1;
        mlp1<128, true>(sm + OFF_W1, sm + OFF_B1, xb, lane, z0, z1);
        __syncwarp();
        xb[lane]      = z0;
        xb[lane + 32] = z1;
        __syncwarp();
        float o0, o1;
        mlp1<64, true>(sm + OFF_W2, sm + OFF_B2, xb, lane, o0, o1);
        out[b * Dm + lane]      = o0;
        out[b * Dm + lane + 32] = o1;
        __syncwarp();
    }
}

// ---------------- launch ---------------------------------------------------
extern "C" void kernel_launch(void* const* d_in, const int* in_sizes, int n_in,
                              void* d_out, int out_size) {
    const int*   nodes_v = (const int*)d_in[0];
    const int*   neigh_u = (const int*)d_in[1];
    const int*   neigh_r = (const int*)d_in[2];
    const float* embed_u = (const float*)d_in[3];
    const float* embed_i = (const float*)d_in[4];
    const float* embed_r = (const float*)d_in[5];
    const float* gv_w1 = (const float*)d_in[6];
    const float* gv_b1 = (const float*)d_in[7];
    const float* gv_w2 = (const float*)d_in[8];
    const float* gv_b2 = (const float*)d_in[9];
    const float* gv_w3 = (const float*)d_in[10];
    const float* gv_b3 = (const float*)d_in[11];
    const float* at_w1 = (const float*)d_in[12];
    const float* at_b1 = (const float*)d_in[13];
    const float* at_w2 = (const float*)d_in[14];
    const float* at_b2 = (const float*)d_in[15];
    const float* at_w3 = (const float*)d_in[16];
    const float* at_b3 = (const float*)d_in[17];
    const float* wr1_w = (const float*)d_in[18];
    const float* wr1_b = (const float*)d_in[19];
    const float* wr2_w = (const float*)d_in[20];
    const float* wr2_b = (const float*)d_in[21];
    float* out = (float*)d_out;

    int nsm = 148;
    cudaDeviceGetAttribute(&nsm, cudaDevAttrMultiProcessorCount, 0);

    const size_t s1 = SMEM1_FLOATS * sizeof(float);
    const size_t s2 = SMEM2_FLOATS * sizeof(float);
    cudaFuncSetAttribute(k_rows, cudaFuncAttributeMaxDynamicSharedMemorySize, (int)s1);
    cudaFuncSetAttribute(k_agg,  cudaFuncAttributeMaxDynamicSharedMemorySize, (int)s2);

    k_rows<<<nsm, 512, s1>>>(nodes_v, neigh_u, neigh_r, embed_u, embed_i, embed_r,
                             gv_w1, gv_b1, gv_w2, gv_b2, gv_w3, gv_b3,
                             at_w1, at_b1, at_w2, at_b2, at_w3, at_b3);
    k_agg<<<512, 256, s2>>>(nodes_v, embed_i, wr1_w, wr1_b, wr2_w, wr2_b, out);
}